// round 2
// baseline (speedup 1.0000x reference)
#include <cuda_runtime.h>
#include <cuda_bf16.h>

#define N_NODES 50000
#define N_EDGES 800000
#define N_GRAPHS 512
#define D 64
#define ED 16

// ---------------- scratch (static device allocations) ----------------
__device__ float g_h1[N_NODES * D];     // 12.8 MB
__device__ float g_h2[N_NODES * D];     // 12.8 MB
__device__ float g_aggr[N_NODES * D];   // 12.8 MB
__device__ float g_psum[N_GRAPHS];
__device__ float g_pcnt[N_GRAPHS];

__device__ __forceinline__ const float* pick_h(const float* x, int sel) {
    return sel == 0 ? x : (sel == 1 ? g_h1 : g_h2);
}
__device__ __forceinline__ float* pick_hw(int sel) {
    return sel == 1 ? g_h1 : g_h2;
}

// ---------------- zeroing ----------------
__global__ void zero_aggr_kernel() {
    int i = blockIdx.x * blockDim.x + threadIdx.x;
    float4* p = (float4*)g_aggr;
    const int n = N_NODES * D / 4;
    for (; i < n; i += gridDim.x * blockDim.x) p[i] = make_float4(0.f, 0.f, 0.f, 0.f);
}

__global__ void zero_pool_kernel() {
    int i = threadIdx.x;
    if (i < N_GRAPHS) { g_psum[i] = 0.f; g_pcnt[i] = 0.f; }
}

// ---------------- edge phase: msg = relu(h[src] + ea@We + be); atomic scatter to dst ----------------
// 16 threads per edge, each handles 4 consecutive columns (float4 of the 64-wide row).
__global__ void edge_kernel(const float* __restrict__ x, int hin_sel,
                            const int* __restrict__ src,
                            const int* __restrict__ dst,
                            const float* __restrict__ ea,
                            const float* __restrict__ We,
                            const float* __restrict__ be) {
    __shared__ float sWe[ED * D];
    __shared__ float sbe[D];
    int tid = threadIdx.x;
    for (int i = tid; i < ED * D; i += 256) sWe[i] = We[i];
    if (tid < D) sbe[tid] = be[tid];
    __syncthreads();

    const float* __restrict__ h = pick_h(x, hin_sel);

    int eid = blockIdx.x * 16 + (tid >> 4);
    if (eid >= N_EDGES) return;
    int t = tid & 15;
    int c = t * 4;

    int s = src[eid];
    int d = dst[eid];

    const float4* eap = (const float4*)(ea + (long long)eid * ED);
    float4 e0 = eap[0], e1 = eap[1], e2 = eap[2], e3 = eap[3];
    float eav[16] = {e0.x, e0.y, e0.z, e0.w, e1.x, e1.y, e1.z, e1.w,
                     e2.x, e2.y, e2.z, e2.w, e3.x, e3.y, e3.z, e3.w};

    float a0 = sbe[c + 0], a1 = sbe[c + 1], a2 = sbe[c + 2], a3 = sbe[c + 3];
#pragma unroll
    for (int k = 0; k < 16; k++) {
        float v = eav[k];
        const float* w = &sWe[k * D + c];
        a0 += v * w[0];
        a1 += v * w[1];
        a2 += v * w[2];
        a3 += v * w[3];
    }

    float4 hs = *(const float4*)(h + (long long)s * D + c);
    a0 = fmaxf(hs.x + a0, 0.f);
    a1 = fmaxf(hs.y + a1, 0.f);
    a2 = fmaxf(hs.z + a2, 0.f);
    a3 = fmaxf(hs.w + a3, 0.f);

    float* ap = g_aggr + (long long)d * D + c;
    atomicAdd(ap + 0, a0);
    atomicAdd(ap + 1, a1);
    atomicAdd(ap + 2, a2);
    atomicAdd(ap + 3, a3);
}

// ---------------- node phase: h_out = relu((h_in + aggr) @ W + b) ----------------
// 256 threads = 4 nodes x 64 output columns.
__global__ void node_kernel(const float* __restrict__ x, int hin_sel, int hout_sel,
                            const float* __restrict__ W,
                            const float* __restrict__ b) {
    __shared__ float sW[D * D];
    __shared__ float sb[D];
    __shared__ float sz[4][D];
    int tid = threadIdx.x;
    for (int i = tid; i < D * D; i += 256) sW[i] = W[i];
    if (tid < D) sb[tid] = b[tid];

    const float* __restrict__ h_in = pick_h(x, hin_sel);
    float* __restrict__ h_out = pick_hw(hout_sel);

    int g = tid >> 6;
    int c = tid & 63;
    int node = blockIdx.x * 4 + g;
    if (node < N_NODES) sz[g][c] = h_in[(long long)node * D + c] + g_aggr[(long long)node * D + c];
    __syncthreads();
    if (node >= N_NODES) return;

    float acc = sb[c];
#pragma unroll
    for (int k = 0; k < D; k++) acc += sz[g][k] * sW[k * D + c];
    h_out[(long long)node * D + c] = fmaxf(acc, 0.f);
}

// ---------------- layer 3 + pooling: s = (h+aggr)·W_out + b_out; scatter into per-graph sums ----------------
// one warp per node
__global__ void final_node_kernel(const float* __restrict__ x, int hin_sel,
                                  const float* __restrict__ Wout,
                                  const float* __restrict__ bout,
                                  const int* __restrict__ batch) {
    const float* __restrict__ h_in = pick_h(x, hin_sel);
    int warp = threadIdx.x >> 5;
    int lane = threadIdx.x & 31;
    int node = blockIdx.x * 8 + warp;
    if (node >= N_NODES) return;

    float acc = 0.f;
#pragma unroll
    for (int k = lane; k < D; k += 32)
        acc += (h_in[(long long)node * D + k] + g_aggr[(long long)node * D + k]) * Wout[k];
#pragma unroll
    for (int o = 16; o > 0; o >>= 1) acc += __shfl_down_sync(0xffffffffu, acc, o);

    if (lane == 0) {
        int bgr = batch[node];
        atomicAdd(&g_psum[bgr], acc + bout[0]);
        atomicAdd(&g_pcnt[bgr], 1.f);
    }
}

// ---------------- finalize: mean-pool divide, BatchNorm1d(1) training stats, sigmoid ----------------
__global__ void finalize_kernel(const float* __restrict__ gamma,
                                const float* __restrict__ beta,
                                float* __restrict__ out) {
    __shared__ float red[N_GRAPHS];
    int t = threadIdx.x;
    float p = g_psum[t] / fmaxf(g_pcnt[t], 1.f);

    red[t] = p;
    __syncthreads();
    for (int o = N_GRAPHS / 2; o > 0; o >>= 1) {
        if (t < o) red[t] += red[t + o];
        __syncthreads();
    }
    float m = red[0] / (float)N_GRAPHS;
    __syncthreads();

    float dlt = p - m;
    red[t] = dlt * dlt;
    __syncthreads();
    for (int o = N_GRAPHS / 2; o > 0; o >>= 1) {
        if (t < o) red[t] += red[t + o];
        __syncthreads();
    }
    float v = red[0] / (float)N_GRAPHS;

    float y = gamma[0] * (p - m) / sqrtf(v + 1e-5f) + beta[0];
    out[t] = 1.f / (1.f + expf(-y));
}

// ---------------- launch ----------------
extern "C" void kernel_launch(void* const* d_in, const int* in_sizes, int n_in,
                              void* d_out, int out_size) {
    const float* x     = (const float*)d_in[0];
    const int*   ei    = (const int*)d_in[1];
    const float* ea    = (const float*)d_in[2];
    const int*   batch = (const int*)d_in[3];
    const float* Wh    = (const float*)d_in[4];
    const float* bh    = (const float*)d_in[5];
    const float* We    = (const float*)d_in[6];
    const float* be    = (const float*)d_in[7];
    const float* Wout  = (const float*)d_in[8];
    const float* bout  = (const float*)d_in[9];
    const float* gamma = (const float*)d_in[10];
    const float* beta  = (const float*)d_in[11];
    float* out = (float*)d_out;

    const int* src = ei;
    const int* dst = ei + N_EDGES;

    const int EDGE_BLOCKS = (N_EDGES + 15) / 16;                 // 50000
    const int NODE_BLOCKS = (N_NODES + 3) / 4;                   // 12500
    const int FNODE_BLOCKS = (N_NODES + 7) / 8;                  // 6250
    const int ZERO_BLOCKS = 512;

    zero_pool_kernel<<<1, N_GRAPHS>>>();

    // layer sequence: hin sel 0=x, 1=g_h1, 2=g_h2
    // l0: x   -> g_h1
    // l1: h1  -> g_h2
    // l2: h2  -> g_h1
    // l3: h1  -> pooled
    int hin[4]  = {0, 1, 2, 1};
    int hout[3] = {1, 2, 1};

    for (int l = 0; l < 3; l++) {
        zero_aggr_kernel<<<ZERO_BLOCKS, 256>>>();
        edge_kernel<<<EDGE_BLOCKS, 256>>>(x, hin[l], src, dst, ea,
                                          We + l * ED * D, be + l * D);
        node_kernel<<<NODE_BLOCKS, 256>>>(x, hin[l], hout[l],
                                          Wh + l * D * D, bh + l * D);
    }
    zero_aggr_kernel<<<ZERO_BLOCKS, 256>>>();
    edge_kernel<<<EDGE_BLOCKS, 256>>>(x, hin[3], src, dst, ea,
                                      We + 3 * ED * D, be + 3 * D);
    final_node_kernel<<<FNODE_BLOCKS, 256>>>(x, hin[3], Wout, bout, batch);
    finalize_kernel<<<1, N_GRAPHS>>>(gamma, beta, out);
}

// round 3
// speedup vs baseline: 1.2438x; 1.2438x over previous
#include <cuda_runtime.h>
#include <cuda_bf16.h>

#define N_NODES 50000
#define N_EDGES 800000
#define N_GRAPHS 512
#define D 64
#define ED 16

// ---------------- scratch (static device allocations; zero-initialized at load) ----------------
__device__ float g_h1[N_NODES * D];     // 12.8 MB
__device__ float g_h2[N_NODES * D];     // 12.8 MB
__device__ float g_aggr[N_NODES * D];   // 12.8 MB  (invariant: zero at entry to each edge phase)
__device__ float g_psum[N_GRAPHS];      // (invariant: zero at entry to final_node phase)
__device__ float g_pcnt[N_GRAPHS];

__device__ __forceinline__ const float* pick_h(const float* x, int sel) {
    return sel == 0 ? x : (sel == 1 ? g_h1 : g_h2);
}
__device__ __forceinline__ float* pick_hw(int sel) {
    return sel == 1 ? g_h1 : g_h2;
}

__device__ __forceinline__ void red_add_v4(float* p, float a, float b, float c, float d) {
    asm volatile("red.global.add.v4.f32 [%0], {%1, %2, %3, %4};"
                 :: "l"(p), "f"(a), "f"(b), "f"(c), "f"(d) : "memory");
}

// ---------------- edge phase: msg = relu(h[src] + ea@We + be); vectorized red scatter ----------------
// 16 threads per edge, each handles 4 consecutive columns (one float4 of the 64-wide row).
__global__ void edge_kernel(const float* __restrict__ x, int hin_sel,
                            const int* __restrict__ src,
                            const int* __restrict__ dst,
                            const float* __restrict__ ea,
                            const float* __restrict__ We,
                            const float* __restrict__ be) {
    __shared__ float sWe[ED * D];
    __shared__ float sbe[D];
    int tid = threadIdx.x;
    for (int i = tid; i < ED * D; i += 256) sWe[i] = We[i];
    if (tid < D) sbe[tid] = be[tid];
    __syncthreads();

    const float* __restrict__ h = pick_h(x, hin_sel);

    int eid = blockIdx.x * 16 + (tid >> 4);
    if (eid >= N_EDGES) return;
    int t = tid & 15;
    int c = t * 4;

    int s = src[eid];
    int d = dst[eid];

    const float4* eap = (const float4*)(ea + (long long)eid * ED);
    float4 e0 = eap[0], e1 = eap[1], e2 = eap[2], e3 = eap[3];
    float eav[16] = {e0.x, e0.y, e0.z, e0.w, e1.x, e1.y, e1.z, e1.w,
                     e2.x, e2.y, e2.z, e2.w, e3.x, e3.y, e3.z, e3.w};

    float4 bv = *(const float4*)&sbe[c];
    float a0 = bv.x, a1 = bv.y, a2 = bv.z, a3 = bv.w;
#pragma unroll
    for (int k = 0; k < 16; k++) {
        float v = eav[k];
        float4 w = *(const float4*)&sWe[k * D + c];
        a0 += v * w.x;
        a1 += v * w.y;
        a2 += v * w.z;
        a3 += v * w.w;
    }

    float4 hs = *(const float4*)(h + (long long)s * D + c);
    a0 = fmaxf(hs.x + a0, 0.f);
    a1 = fmaxf(hs.y + a1, 0.f);
    a2 = fmaxf(hs.z + a2, 0.f);
    a3 = fmaxf(hs.w + a3, 0.f);

    red_add_v4(g_aggr + (long long)d * D + c, a0, a1, a2, a3);
}

// ---------------- node phase: h_out = relu((h_in + aggr) @ W + b); re-zeroes aggr ----------------
// 256 threads = 16 nodes x 16 quads; each thread computes 4 consecutive output cols (float4).
__global__ void node_kernel(const float* __restrict__ x, int hin_sel, int hout_sel,
                            const float* __restrict__ W,
                            const float* __restrict__ b) {
    __shared__ float4 sW4[D * 16];      // sW4[k*16 + q] = W[k][4q..4q+3]
    __shared__ float  sz[16][D];
    __shared__ float  sb[D];
    int tid = threadIdx.x;

    const float4* W4 = (const float4*)W;
    for (int i = tid; i < D * 16; i += 256) sW4[i] = W4[i];
    if (tid < D) sb[tid] = b[tid];

    const float* __restrict__ h_in = pick_h(x, hin_sel);
    float* __restrict__ h_out = pick_hw(hout_sel);

    int g = tid >> 4;          // node within block (0..15)
    int q = tid & 15;          // quad (0..15) -> columns 4q..4q+3
    long long node = (long long)blockIdx.x * 16 + g;
    bool valid = node < N_NODES;

    if (valid) {
        long long off = node * D + q * 4;
        float4 hv = *(const float4*)(h_in + off);
        float4 av = *(float4*)(g_aggr + off);
        float4 z = make_float4(hv.x + av.x, hv.y + av.y, hv.z + av.z, hv.w + av.w);
        *(float4*)&sz[g][q * 4] = z;
        // re-zero aggr for the next edge phase
        *(float4*)(g_aggr + off) = make_float4(0.f, 0.f, 0.f, 0.f);
    }
    __syncthreads();
    if (!valid) return;

    float4 bv = *(const float4*)&sb[q * 4];
    float a0 = bv.x, a1 = bv.y, a2 = bv.z, a3 = bv.w;
#pragma unroll
    for (int k = 0; k < D; k++) {
        float zk = sz[g][k];
        float4 w = sW4[k * 16 + q];
        a0 += zk * w.x;
        a1 += zk * w.y;
        a2 += zk * w.z;
        a3 += zk * w.w;
    }

    float4 r = make_float4(fmaxf(a0, 0.f), fmaxf(a1, 0.f), fmaxf(a2, 0.f), fmaxf(a3, 0.f));
    *(float4*)(h_out + node * D + q * 4) = r;
}

// ---------------- layer 3 + pooling; re-zeroes aggr ----------------
// one warp per node
__global__ void final_node_kernel(const float* __restrict__ x, int hin_sel,
                                  const float* __restrict__ Wout,
                                  const float* __restrict__ bout,
                                  const int* __restrict__ batch) {
    const float* __restrict__ h_in = pick_h(x, hin_sel);
    int warp = threadIdx.x >> 5;
    int lane = threadIdx.x & 31;
    long long node = (long long)blockIdx.x * 8 + warp;
    if (node >= N_NODES) return;

    float acc = 0.f;
#pragma unroll
    for (int k = lane; k < D; k += 32) {
        long long off = node * D + k;
        acc += (h_in[off] + g_aggr[off]) * Wout[k];
        g_aggr[off] = 0.f;      // re-zero for next replay
    }
#pragma unroll
    for (int o = 16; o > 0; o >>= 1) acc += __shfl_down_sync(0xffffffffu, acc, o);

    if (lane == 0) {
        int bgr = batch[node];
        atomicAdd(&g_psum[bgr], acc + bout[0]);
        atomicAdd(&g_pcnt[bgr], 1.f);
    }
}

// ---------------- finalize: mean-pool, BatchNorm1d(1) training stats, sigmoid; re-zeroes pool ----------------
__global__ void finalize_kernel(const float* __restrict__ gamma,
                                const float* __restrict__ beta,
                                float* __restrict__ out) {
    __shared__ float red[N_GRAPHS];
    int t = threadIdx.x;
    float p = g_psum[t] / fmaxf(g_pcnt[t], 1.f);
    // re-zero pooling accumulators for the next replay
    g_psum[t] = 0.f;
    g_pcnt[t] = 0.f;

    red[t] = p;
    __syncthreads();
    for (int o = N_GRAPHS / 2; o > 0; o >>= 1) {
        if (t < o) red[t] += red[t + o];
        __syncthreads();
    }
    float m = red[0] / (float)N_GRAPHS;
    __syncthreads();

    float dlt = p - m;
    red[t] = dlt * dlt;
    __syncthreads();
    for (int o = N_GRAPHS / 2; o > 0; o >>= 1) {
        if (t < o) red[t] += red[t + o];
        __syncthreads();
    }
    float v = red[0] / (float)N_GRAPHS;

    float y = gamma[0] * (p - m) / sqrtf(v + 1e-5f) + beta[0];
    out[t] = 1.f / (1.f + expf(-y));
}

// ---------------- launch ----------------
extern "C" void kernel_launch(void* const* d_in, const int* in_sizes, int n_in,
                              void* d_out, int out_size) {
    const float* x     = (const float*)d_in[0];
    const int*   ei    = (const int*)d_in[1];
    const float* ea    = (const float*)d_in[2];
    const int*   batch = (const int*)d_in[3];
    const float* Wh    = (const float*)d_in[4];
    const float* bh    = (const float*)d_in[5];
    const float* We    = (const float*)d_in[6];
    const float* be    = (const float*)d_in[7];
    const float* Wout  = (const float*)d_in[8];
    const float* bout  = (const float*)d_in[9];
    const float* gamma = (const float*)d_in[10];
    const float* beta  = (const float*)d_in[11];
    float* out = (float*)d_out;

    const int* src = ei;
    const int* dst = ei + N_EDGES;

    const int EDGE_BLOCKS  = (N_EDGES + 15) / 16;    // 50000
    const int NODE_BLOCKS  = (N_NODES + 15) / 16;    // 3125
    const int FNODE_BLOCKS = (N_NODES + 7) / 8;      // 6250

    // layer sequence: hin sel 0=x, 1=g_h1, 2=g_h2
    int hin[4]  = {0, 1, 2, 1};
    int hout[3] = {1, 2, 1};

    for (int l = 0; l < 3; l++) {
        edge_kernel<<<EDGE_BLOCKS, 256>>>(x, hin[l], src, dst, ea,
                                          We + l * ED * D, be + l * D);
        node_kernel<<<NODE_BLOCKS, 256>>>(x, hin[l], hout[l],
                                          Wh + l * D * D, bh + l * D);
    }
    edge_kernel<<<EDGE_BLOCKS, 256>>>(x, hin[3], src, dst, ea,
                                      We + 3 * ED * D, be + 3 * D);
    final_node_kernel<<<FNODE_BLOCKS, 256>>>(x, hin[3], Wout, bout, batch);
    finalize_kernel<<<1, N_GRAPHS>>>(gamma, beta, out);
}